// round 1
// baseline (speedup 1.0000x reference)
#include <cuda_runtime.h>
#include <math.h>

// Problem constants
constexpr int NB   = 128;    // batch
constexpr int NP   = 196;    // num patches
constexpr int FEAT = 2048;   // image feature dim
constexpr int E    = 512;    // embedding dim
constexpr int D    = 512;    // hidden dim
constexpr int V    = 10000;  // vocab
constexpr int L    = 52;     // caption length
constexpr int T    = 51;     // decode steps (L-1)
constexpr int G    = 4 * D;  // gates width 2048
constexpr int R    = NB * T; // 6528 rows

// -------- device scratch (static allocation only; no cudaMalloc allowed) ----
__device__ float d_fm[NB * FEAT];      // sorted mean features
__device__ float d_hst[NB * D];        // h state
__device__ float d_cst[NB * D];        // c state
__device__ float d_gates[NB * G];      // per-step gates
__device__ float d_xproj[(size_t)R * G]; // precomputed x@Wih^T + biases (53.5MB)
__device__ float d_Hbuf[(size_t)R * D];  // h_new per (b,t) for word projection
__device__ int   d_sortind[NB];
__device__ int   d_dlen[NB];
__device__ int   d_tok[R];
__device__ float d_bias2[G];           // b_ih + b_hh

// ---------------------------------------------------------------------------
// prep: stable descending argsort (counting), dec_len, token gather,
// bias sum, c-state zero, and the int-output tail of d_out (as float).
// ---------------------------------------------------------------------------
__global__ void prep_kernel(const int* __restrict__ clen,
                            const int* __restrict__ caps,
                            const float* __restrict__ b_ih,
                            const float* __restrict__ b_hh,
                            float* __restrict__ out,
                            int write_tail)
{
    __shared__ int s_len[NB];
    int tid = threadIdx.x;
    s_len[tid] = clen[tid];          // caption_lengths is (B,1)
    __syncthreads();
    int li = s_len[tid];
    int rank = 0;
    #pragma unroll 4
    for (int j = 0; j < NB; j++) {
        int lj = s_len[j];
        rank += (lj > li) || (lj == li && j < tid);
    }
    d_sortind[rank] = tid;           // sort_ind[rank] = tid
    __syncthreads();

    int src = d_sortind[tid];
    int dl  = s_len[src] - 1;
    d_dlen[tid] = dl;

    if (write_tail) {
        float* out_caps = out + (size_t)NB * T * V;
        float* out_dlen = out_caps + (size_t)NB * L;
        float* out_sort = out_dlen + NB;
        out_dlen[tid] = (float)dl;
        out_sort[tid] = (float)src;
        for (int j = 0; j < L; j++) {
            int tk = caps[src * L + j];
            out_caps[tid * L + j] = (float)tk;
            if (j < T) d_tok[tid * T + j] = tk;
        }
    } else {
        for (int j = 0; j < T; j++)
            d_tok[tid * T + j] = caps[src * L + j];
    }

    for (int j = tid; j < G; j += NB)      d_bias2[j] = b_ih[j] + b_hh[j];
    for (int j = tid; j < NB * D; j += NB) d_cst[j] = 0.f;
}

// ---------------------------------------------------------------------------
// mean over patches, applying the sort permutation. One block per output row.
// ---------------------------------------------------------------------------
__global__ void mean_kernel(const float* __restrict__ feats)
{
    int b   = blockIdx.x;
    int src = d_sortind[b];
    const float* base = feats + (size_t)src * NP * FEAT;
    int tid = threadIdx.x;  // 256
    float acc[FEAT / 256];
    #pragma unroll
    for (int j = 0; j < FEAT / 256; j++) acc[j] = 0.f;
    for (int p = 0; p < NP; p++) {
        const float* row = base + (size_t)p * FEAT;
        #pragma unroll
        for (int j = 0; j < FEAT / 256; j++) acc[j] += __ldg(&row[tid + j * 256]);
    }
    #pragma unroll
    for (int j = 0; j < FEAT / 256; j++)
        d_fm[b * FEAT + tid + j * 256] = acc[j] * (1.f / NP);
}

// ---------------------------------------------------------------------------
// Generic C[M,N] = A[M,K] @ B[N,K]^T (+bias[N]) (+Cin) with optional A-row
// gather and optional row-mask (word projection). BM = 16*TM, BN = 64.
// M must be a multiple of BM, K a multiple of 32 (true for all call sites).
// ---------------------------------------------------------------------------
template<int TM>
__global__ void gemm_tn(const float* __restrict__ A, int lda,
                        const int*   __restrict__ aIdx,
                        const float* __restrict__ Bm,
                        const float* __restrict__ bias,
                        const float* __restrict__ Cin, int ldcin,
                        float* __restrict__ Cout, int ldc,
                        int N, int K,
                        const int* __restrict__ dlen)
{
    constexpr int BM = 16 * TM;
    constexpr int BN = 64;
    __shared__ float As[32][BM + 1];
    __shared__ float Bs[32][BN + 1];
    __shared__ int s_any;

    int tid = threadIdx.x;              // 256 threads
    int m0  = blockIdx.x * BM;
    int n0  = blockIdx.y * BN;
    int tx  = tid & 15;
    int ty  = tid >> 4;

    bool maskMode = (dlen != nullptr);
    if (maskMode) {
        if (tid == 0) s_any = 0;
        __syncthreads();
        if (tid < BM) {
            int r = m0 + tid;
            int b = r / T;
            int t = r - b * T;
            if (t < __ldg(&dlen[b])) s_any = 1;
        }
        __syncthreads();
        if (!s_any) {   // whole tile masked: zero-fill, skip GEMM
            #pragma unroll
            for (int i = 0; i < TM; i++) {
                int gm = m0 + ty * TM + i;
                #pragma unroll
                for (int j = 0; j < 4; j++) {
                    int gn = n0 + tx * 4 + j;
                    if (gn < N) Cout[(size_t)gm * ldc + gn] = 0.f;
                }
            }
            return;
        }
    }

    float acc[TM][4];
    #pragma unroll
    for (int i = 0; i < TM; i++)
        #pragma unroll
        for (int j = 0; j < 4; j++) acc[i][j] = 0.f;

    for (int k0 = 0; k0 < K; k0 += 32) {
        #pragma unroll
        for (int i = 0; i < (BM * 32) / 256; i++) {
            int lin = tid + i * 256;
            int m = lin >> 5, k = lin & 31;
            int gm = m0 + m;
            int ar = aIdx ? __ldg(&aIdx[gm]) : gm;
            As[k][m] = __ldg(&A[(size_t)ar * lda + k0 + k]);
        }
        #pragma unroll
        for (int i = 0; i < 8; i++) {
            int lin = tid + i * 256;
            int n = lin >> 5, k = lin & 31;
            int gn = n0 + n;
            Bs[k][n] = (gn < N) ? __ldg(&Bm[(size_t)gn * K + k0 + k]) : 0.f;
        }
        __syncthreads();
        #pragma unroll
        for (int k = 0; k < 32; k++) {
            float bv[4];
            #pragma unroll
            for (int j = 0; j < 4; j++) bv[j] = Bs[k][tx * 4 + j];
            #pragma unroll
            for (int i = 0; i < TM; i++) {
                float av = As[k][ty * TM + i];
                #pragma unroll
                for (int j = 0; j < 4; j++)
                    acc[i][j] = fmaf(av, bv[j], acc[i][j]);
            }
        }
        __syncthreads();
    }

    #pragma unroll
    for (int i = 0; i < TM; i++) {
        int gm = m0 + ty * TM + i;
        bool ok = true;
        if (maskMode) {
            int b = gm / T;
            int t = gm - b * T;
            ok = (t < __ldg(&dlen[b]));
        }
        const float* cin = Cin ? (Cin + (size_t)gm * ldcin) : nullptr;
        #pragma unroll
        for (int j = 0; j < 4; j++) {
            int gn = n0 + tx * 4 + j;
            if (gn < N) {
                float v = acc[i][j];
                if (bias) v += __ldg(&bias[gn]);
                if (cin)  v += cin[gn];
                if (maskMode && !ok) v = 0.f;
                Cout[(size_t)gm * ldc + gn] = v;
            }
        }
    }
}

// ---------------------------------------------------------------------------
// LSTM pointwise: gates -> (i,f,g,o) -> c_new,h_new, masked state update,
// h_new stored to Hbuf for the batched word projection.
// ---------------------------------------------------------------------------
__device__ __forceinline__ float sigmoidf_(float x) {
    return 1.f / (1.f + __expf(-x));
}

__global__ void lstm_pointwise(int t)
{
    int idx = blockIdx.x * blockDim.x + threadIdx.x;  // 65536 = 128*512
    int b = idx >> 9;
    int d = idx & (D - 1);
    const float* g = d_gates + (size_t)b * G;
    float gi = sigmoidf_(g[d]);
    float gf = sigmoidf_(g[D + d]);
    float gg = tanhf(g[2 * D + d]);
    float go = sigmoidf_(g[3 * D + d]);
    float c  = d_cst[idx];
    float cn = gf * c + gi * gg;
    float hn = go * tanhf(cn);
    if (t < d_dlen[b]) { d_cst[idx] = cn; d_hst[idx] = hn; }
    d_Hbuf[(size_t)(b * T + t) * D + d] = hn;
}

// ---------------------------------------------------------------------------
extern "C" void kernel_launch(void* const* d_in, const int* in_sizes, int n_in,
                              void* d_out, int out_size)
{
    const float* feats  = (const float*)d_in[0];
    const int*   caps   = (const int*)  d_in[1];
    const int*   clen   = (const int*)  d_in[2];
    const float* emb    = (const float*)d_in[3];
    const float* att1_w = (const float*)d_in[4];
    const float* att1_b = (const float*)d_in[5];
    const float* w_ih   = (const float*)d_in[6];
    const float* w_hh   = (const float*)d_in[7];
    const float* b_ih   = (const float*)d_in[8];
    const float* b_hh   = (const float*)d_in[9];
    const float* word_w = (const float*)d_in[10];
    const float* word_b = (const float*)d_in[11];
    float* out = (float*)d_out;

    float *fm, *hst, *cst, *gates, *xproj, *Hbuf, *bias2;
    int *sortind, *dlen, *tok;
    cudaGetSymbolAddress((void**)&fm,      d_fm);
    cudaGetSymbolAddress((void**)&hst,     d_hst);
    cudaGetSymbolAddress((void**)&cst,     d_cst);
    cudaGetSymbolAddress((void**)&gates,   d_gates);
    cudaGetSymbolAddress((void**)&xproj,   d_xproj);
    cudaGetSymbolAddress((void**)&Hbuf,    d_Hbuf);
    cudaGetSymbolAddress((void**)&bias2,   d_bias2);
    cudaGetSymbolAddress((void**)&sortind, d_sortind);
    cudaGetSymbolAddress((void**)&dlen,    d_dlen);
    cudaGetSymbolAddress((void**)&tok,     d_tok);

    const long long PRED = (long long)NB * T * V;
    int write_tail = ((long long)out_size >= PRED + NB * L + 2 * NB) ? 1 : 0;

    // 1) sort + prep
    prep_kernel<<<1, NB>>>(clen, caps, b_ih, b_hh, out, write_tail);

    // 2) sorted mean features (reads the 205MB input once)
    mean_kernel<<<NB, 256>>>(feats);

    // 3) h0 = fm @ att1_w^T + att1_b   [128,512] K=2048
    gemm_tn<1><<<dim3(NB / 16, D / 64), 256>>>(
        fm, FEAT, nullptr, att1_w, att1_b, nullptr, 0, hst, D, D, FEAT, nullptr);

    // 4) input projection for ALL steps at once:
    //    xproj[r] = emb_table[tok[r]] @ w_ih^T + (b_ih + b_hh)   [6528,2048] K=512
    gemm_tn<4><<<dim3(R / 64, G / 64), 256>>>(
        emb, E, tok, w_ih, bias2, nullptr, 0, xproj, G, G, E, nullptr);

    // 5) sequential LSTM: per step only h @ w_hh^T remains
    for (int t = 0; t < T; t++) {
        gemm_tn<2><<<dim3(NB / 32, G / 64), 256>>>(
            hst, D, nullptr, w_hh, nullptr,
            xproj + (size_t)t * G, T * G,
            gates, G, G, D, nullptr);
        lstm_pointwise<<<NB * D / 256, 256>>>(t);
    }

    // 6) batched, masked word projection into d_out predictions
    //    pred[r] = valid ? Hbuf[r] @ word_w^T + word_b : 0
    gemm_tn<4><<<dim3(R / 64, (V + 63) / 64), 256>>>(
        Hbuf, D, nullptr, word_w, word_b, nullptr, 0, out, V, V, D, dlen);
}